// round 6
// baseline (speedup 1.0000x reference)
#include <cuda_runtime.h>
#include <cstdint>

// y[t,b,f] = sum_{k=0..20} x[t+k,b,f] * w[f,k], zero-padded past t=T-1.
// Each thread owns TWO adjacent features (one float2 column) and a 64-long
// time strip: 8 fully-unrolled chunks of 8 with a 20-element carried register
// window (rotation = register renaming). Packed fma.rn.f32x2 halves fp32 work.
// NEW: prefetch.global.L2 runs 2 chunks (16 timesteps) ahead of the demand
// loads — zero register / zero scoreboard cost — so demand LDGs hit L2 and
// 16 warps/SM suffice to cover the latency. Stores use st.global.cs so the
// write stream doesn't evict prefetched read lines.

#define FMA_F32X2(d, a, b, c) \
    asm("fma.rn.f32x2 %0, %1, %2, %3;" : "=l"(d) : "l"(a), "l"(b), "l"(c))
#define MUL_F32X2(d, a, b) \
    asm("mul.rn.f32x2 %0, %1, %2;" : "=l"(d) : "l"(a), "l"(b))
#define PREFETCH_L2(p) \
    asm volatile("prefetch.global.L2 [%0];" :: "l"(p))

namespace la {
constexpr int T = 2048;
constexpr int B = 16;
constexpr int F = 1024;
constexpr int CTX = 20;
constexpr int K = 21;                  // CTX + 1 taps
constexpr int BF2 = (B * F) / 2;       // timestep stride in float2 units = 8192
constexpr int TCHUNK = 64;             // t's per thread
constexpr int STEP = 8;                // t's per inner chunk
constexpr int NCHUNK = TCHUNK / STEP;  // 8, fully unrolled
constexpr int PF_DIST = 2 * STEP;      // prefetch 2 chunks ahead
}  // namespace la

__global__ void __launch_bounds__(256, 2)
lookahead_kernel(const unsigned long long* __restrict__ x2,  // x as float2 (u64 bits)
                 const float* __restrict__ w,
                 unsigned long long* __restrict__ y2)
{
    using namespace la;
    const int fpair = blockIdx.x * blockDim.x + threadIdx.x;  // 0..511
    const int b     = blockIdx.y;                             // 0..15
    const int t0    = blockIdx.z * TCHUNK;                    // 0,64,...,1984
    const int f0    = fpair * 2;

    // Pack the two per-feature weight vectors into u64 (lo = f0, hi = f0+1),
    // matching the float2 load layout (.x in low word).
    unsigned long long wk[K];
#pragma unroll
    for (int k = 0; k < K; k++) {
        const unsigned int lo = __float_as_uint(__ldg(&w[(size_t)f0 * K + k]));
        const unsigned int hi = __float_as_uint(__ldg(&w[(size_t)(f0 + 1) * K + k]));
        wk[k] = (unsigned long long)lo | ((unsigned long long)hi << 32);
    }

    const unsigned long long* __restrict__ xp = x2 + (size_t)b * (F / 2) + fpair;
    unsigned long long* __restrict__       yp = y2 + (size_t)b * (F / 2) + fpair;

    // Sliding window: win[0..CTX-1] carried, win[CTX..CTX+STEP-1] fresh loads.
    unsigned long long win[STEP + CTX];

    // Preload first CTX timesteps (t0+19 <= 2003 < T: always in-bounds).
#pragma unroll
    for (int i = 0; i < CTX; i++)
        win[i] = __ldg(&xp[(size_t)(t0 + i) * BF2]);

#pragma unroll
    for (int c = 0; c < NCHUNK; c++) {
        const int tb = t0 + c * STEP;

        // Prefetch the timesteps chunk c+2 will demand-load (registerless,
        // scoreboardless). Slight over-run past TCHUNK warms the next CTA's
        // region; guard only against the true end of the tensor.
#pragma unroll
        for (int i = 0; i < STEP; i++) {
            const int tp = tb + CTX + PF_DIST + i;
            if (tp < T) PREFETCH_L2(&xp[(size_t)tp * BF2]);
        }

        // Demand-load STEP new timesteps; zero past the tail (predicated).
#pragma unroll
        for (int i = 0; i < STEP; i++) {
            const int t = tb + CTX + i;
            win[CTX + i] = (t < T) ? __ldg(&xp[(size_t)t * BF2]) : 0ULL;
        }

        // 8 outputs x (1 mul + 20 fma) packed f32x2 each; streaming stores.
#pragma unroll
        for (int i = 0; i < STEP; i++) {
            unsigned long long acc;
            MUL_F32X2(acc, win[i], wk[0]);
#pragma unroll
            for (int k = 1; k < K; k++)
                FMA_F32X2(acc, win[i + k], wk[k], acc);
            __stcs(&yp[(size_t)(tb + i) * BF2], acc);
        }

        // Rotate carried window — pure renaming under full unroll.
#pragma unroll
        for (int i = 0; i < CTX; i++)
            win[i] = win[STEP + i];
    }
}

extern "C" void kernel_launch(void* const* d_in, const int* in_sizes, int n_in,
                              void* d_out, int out_size)
{
    using namespace la;
    (void)in_sizes; (void)n_in; (void)out_size;
    const unsigned long long* x2 = (const unsigned long long*)d_in[0];  // x: (T,B,F) f32
    const float*              w  = (const float*)d_in[1];               // weight: (F,21) f32
    // d_in[2] = tail_padding (int, ==1): baked into the zero-fill guard.
    unsigned long long* y2 = (unsigned long long*)d_out;                // y: (T,B,F) f32

    dim3 block(256, 1, 1);
    dim3 grid((F / 2) / 256, B, T / TCHUNK);  // (2, 16, 32) = 1024 blocks
    lookahead_kernel<<<grid, block>>>(x2, w, y2);
}

// round 7
// speedup vs baseline: 1.0323x; 1.0323x over previous
#include <cuda_runtime.h>
#include <cstdint>

// y[t,b,f] = sum_{k=0..20} x[t+k,b,f] * w[f,k], zero-padded past t=T-1.
// Each thread owns TWO adjacent features (one float2 column) and a 64-long
// time strip: 8 fully-unrolled chunks of 8 with a 20-element carried register
// window (rotation = register renaming). Packed fma.rn.f32x2 halves fp32 work.
// NEW: prefetch.global.L2 runs 2 chunks (16 timesteps) ahead of the demand
// loads — zero register / zero scoreboard cost — so demand LDGs hit L2 and
// 16 warps/SM suffice to cover the latency. Stores use st.global.cs so the
// write stream doesn't evict prefetched read lines.

#define FMA_F32X2(d, a, b, c) \
    asm("fma.rn.f32x2 %0, %1, %2, %3;" : "=l"(d) : "l"(a), "l"(b), "l"(c))
#define MUL_F32X2(d, a, b) \
    asm("mul.rn.f32x2 %0, %1, %2;" : "=l"(d) : "l"(a), "l"(b))
#define PREFETCH_L2(p) \
    asm volatile("prefetch.global.L2 [%0];" :: "l"(p))

namespace la {
constexpr int T = 2048;
constexpr int B = 16;
constexpr int F = 1024;
constexpr int CTX = 20;
constexpr int K = 21;                  // CTX + 1 taps
constexpr int BF2 = (B * F) / 2;       // timestep stride in float2 units = 8192
constexpr int TCHUNK = 64;             // t's per thread
constexpr int STEP = 8;                // t's per inner chunk
constexpr int NCHUNK = TCHUNK / STEP;  // 8, fully unrolled
constexpr int PF_DIST = 2 * STEP;      // prefetch 2 chunks ahead
}  // namespace la

__global__ void __launch_bounds__(256, 2)
lookahead_kernel(const unsigned long long* __restrict__ x2,  // x as float2 (u64 bits)
                 const float* __restrict__ w,
                 unsigned long long* __restrict__ y2)
{
    using namespace la;
    const int fpair = blockIdx.x * blockDim.x + threadIdx.x;  // 0..511
    const int b     = blockIdx.y;                             // 0..15
    const int t0    = blockIdx.z * TCHUNK;                    // 0,64,...,1984
    const int f0    = fpair * 2;

    // Pack the two per-feature weight vectors into u64 (lo = f0, hi = f0+1),
    // matching the float2 load layout (.x in low word).
    unsigned long long wk[K];
#pragma unroll
    for (int k = 0; k < K; k++) {
        const unsigned int lo = __float_as_uint(__ldg(&w[(size_t)f0 * K + k]));
        const unsigned int hi = __float_as_uint(__ldg(&w[(size_t)(f0 + 1) * K + k]));
        wk[k] = (unsigned long long)lo | ((unsigned long long)hi << 32);
    }

    const unsigned long long* __restrict__ xp = x2 + (size_t)b * (F / 2) + fpair;
    unsigned long long* __restrict__       yp = y2 + (size_t)b * (F / 2) + fpair;

    // Sliding window: win[0..CTX-1] carried, win[CTX..CTX+STEP-1] fresh loads.
    unsigned long long win[STEP + CTX];

    // Preload first CTX timesteps (t0+19 <= 2003 < T: always in-bounds).
#pragma unroll
    for (int i = 0; i < CTX; i++)
        win[i] = __ldg(&xp[(size_t)(t0 + i) * BF2]);

#pragma unroll
    for (int c = 0; c < NCHUNK; c++) {
        const int tb = t0 + c * STEP;

        // Prefetch the timesteps chunk c+2 will demand-load (registerless,
        // scoreboardless). Slight over-run past TCHUNK warms the next CTA's
        // region; guard only against the true end of the tensor.
#pragma unroll
        for (int i = 0; i < STEP; i++) {
            const int tp = tb + CTX + PF_DIST + i;
            if (tp < T) PREFETCH_L2(&xp[(size_t)tp * BF2]);
        }

        // Demand-load STEP new timesteps; zero past the tail (predicated).
#pragma unroll
        for (int i = 0; i < STEP; i++) {
            const int t = tb + CTX + i;
            win[CTX + i] = (t < T) ? __ldg(&xp[(size_t)t * BF2]) : 0ULL;
        }

        // 8 outputs x (1 mul + 20 fma) packed f32x2 each; streaming stores.
#pragma unroll
        for (int i = 0; i < STEP; i++) {
            unsigned long long acc;
            MUL_F32X2(acc, win[i], wk[0]);
#pragma unroll
            for (int k = 1; k < K; k++)
                FMA_F32X2(acc, win[i + k], wk[k], acc);
            __stcs(&yp[(size_t)(tb + i) * BF2], acc);
        }

        // Rotate carried window — pure renaming under full unroll.
#pragma unroll
        for (int i = 0; i < CTX; i++)
            win[i] = win[STEP + i];
    }
}

extern "C" void kernel_launch(void* const* d_in, const int* in_sizes, int n_in,
                              void* d_out, int out_size)
{
    using namespace la;
    (void)in_sizes; (void)n_in; (void)out_size;
    const unsigned long long* x2 = (const unsigned long long*)d_in[0];  // x: (T,B,F) f32
    const float*              w  = (const float*)d_in[1];               // weight: (F,21) f32
    // d_in[2] = tail_padding (int, ==1): baked into the zero-fill guard.
    unsigned long long* y2 = (unsigned long long*)d_out;                // y: (T,B,F) f32

    dim3 block(256, 1, 1);
    dim3 grid((F / 2) / 256, B, T / TCHUNK);  // (2, 16, 32) = 1024 blocks
    lookahead_kernel<<<grid, block>>>(x2, w, y2);
}